// round 16
// baseline (speedup 1.0000x reference)
#include <cuda_runtime.h>
#include <cuda_fp16.h>
#include <cstdint>

#define NB 4
#define NN 2048
#define NE 256
#define NH 4
#define ND 64
#define NE2 512
#define NTOK 16384               // 2 * B * N
#define PER (NB*NH*NN*ND)
// 64^-0.25 * sqrt(log2(e)) — folds exp->exp2 conversion into both q and k
#define QK_SCALE2 0.4246609001428604f

// ---------------- scratch (device globals; no allocation allowed) ----------
__device__ __half g_qkh[2][PER];          // fp16 q/k (scaled, incl sqrt(log2e))
__device__ __half g_vh [2][PER];          // fp16 v
__device__ __half g_amh[NTOK*NE];         // attention out fp16
__device__ float  g_h1 [NTOK*NE2];        // FFN1 out raw fp32
__device__ __half g_hg [NTOK*NE2];        // LN+gelu out fp16
__device__ __half g_xh [NTOK*NE];         // x0|x1 fp16
// weights fp16
__device__ __half g_wqkh[NE*NE], g_wvh[NE*NE];      // transposed [n][k]
__device__ __half g_w2h[NE2*NE];                     // W2^T [256][512]
__device__ __half g_w1bt[NE2*NE];                    // W1b^T [512][256]
__device__ __half g_worm[NE*NE];                     // Wo row-major [256][256]
__device__ __half g_w1f[NE2*NE2];                    // [n=512][k=512]: W1a^T | Wf^T
__device__ float  g_bf[NE2];                         // fused bias b1 + bo@W1b

// ---------------- helpers ---------------------------------------------------
__device__ __forceinline__ uint32_t f2h2(float lo, float hi) {
    uint32_t r; asm("cvt.rn.f16x2.f32 %0, %1, %2;" : "=r"(r) : "f"(hi), "f"(lo));
    return r;
}
__device__ __forceinline__ uint32_t hex2(uint32_t x) {
    uint32_t r; asm("ex2.approx.f16x2 %0, %1;" : "=r"(r) : "r"(x)); return r;
}
__device__ __forceinline__ void cpa16(uint32_t s, const void* g) {
    asm volatile("cp.async.cg.shared.global [%0], [%1], 16;" :: "r"(s), "l"(g));
}
__device__ __forceinline__ void cp_commit() { asm volatile("cp.async.commit_group;"); }
template<int N> __device__ __forceinline__ void cp_wait() {
    asm volatile("cp.async.wait_group %0;" :: "n"(N));
}
__device__ __forceinline__ void mma16(float* d, const uint32_t* a, const uint32_t* b) {
    asm("mma.sync.aligned.m16n8k16.row.col.f32.f16.f16.f32 "
        "{%0,%1,%2,%3}, {%4,%5,%6,%7}, {%8,%9}, {%0,%1,%2,%3};\n"
        : "+f"(d[0]), "+f"(d[1]), "+f"(d[2]), "+f"(d[3])
        : "r"(a[0]), "r"(a[1]), "r"(a[2]), "r"(a[3]), "r"(b[0]), "r"(b[1]));
}
__device__ __forceinline__ void ldsm4(uint32_t* r, uint32_t addr) {
    asm("ldmatrix.sync.aligned.m8n8.x4.shared.b16 {%0,%1,%2,%3}, [%4];"
        : "=r"(r[0]), "=r"(r[1]), "=r"(r[2]), "=r"(r[3]) : "r"(addr));
}
__device__ __forceinline__ void ldsm4t(uint32_t* r, uint32_t addr) {
    asm("ldmatrix.sync.aligned.m8n8.x4.trans.shared.b16 {%0,%1,%2,%3}, [%4];"
        : "=r"(r[0]), "=r"(r[1]), "=r"(r[2]), "=r"(r[3]) : "r"(addr));
}

// ---------------- x -> fp16 --------------------------------------------------
__global__ void cvt_x(const float* __restrict__ x0, const float* __restrict__ x1)
{
    int i = blockIdx.x * 256 + threadIdx.x;    // 8-elem chunks, total 524288
    const float4* s = (i < 262144) ? (const float4*)x0 : (const float4*)x1;
    int j = (i < 262144) ? i : i - 262144;
    float4 a = s[2 * j], b = s[2 * j + 1];
    uint4 o;
    o.x = f2h2(a.x, a.y); o.y = f2h2(a.z, a.w);
    o.z = f2h2(b.x, b.y); o.w = f2h2(b.z, b.w);
    ((uint4*)g_xh)[i] = o;
}

// ---------------- weight conversions in ONE launch ---------------------------
// Transposes Wqk/Wv/W1/W2; W1^T split: k<256 -> g_w1f, k>=256 -> g_w1bt.
// Wo converted to fp16 row-major (for the Wf prep GEMM).
__global__ void cvt_wT_all(const float* __restrict__ Wqk, const float* __restrict__ Wv,
                           const float* __restrict__ Wo,  const float* __restrict__ W1,
                           const float* __restrict__ W2)
{
    int bid = blockIdx.x;
    if (bid >= 512) {   // Wo row-major cvt: 64 blocks x 1024 elems
        int idx = (bid - 512) * 1024 + threadIdx.x * 4;
        float4 v = *(const float4*)&Wo[idx];
        uint2 w; w.x = f2h2(v.x, v.y); w.y = f2h2(v.z, v.w);
        *(uint2*)&g_worm[idx] = w;
        return;
    }
    __shared__ float t[32][33];
    const float* s; int K, N, tile;
    if (bid < 64)       { s = Wqk; K = 256; N = 256; tile = bid; }
    else if (bid < 128) { s = Wv;  K = 256; N = 256; tile = bid - 64; }
    else if (bid < 384) { s = W1;  K = 512; N = 512; tile = bid - 128; }
    else                { s = W2;  K = 512; N = 256; tile = bid - 384; }
    int tn = N / 32;
    int k0 = (tile / tn) * 32, n0 = (tile % tn) * 32;
    int tx = threadIdx.x & 31, ty = threadIdx.x >> 5;   // 256 threads = 32x8
#pragma unroll
    for (int i = 0; i < 4; i++)
        t[ty + i * 8][tx] = s[(size_t)(k0 + ty + i * 8) * N + n0 + tx];
    __syncthreads();
    __half* d; int dstride, dk0;
    if (bid < 64)       { d = g_wqkh; dstride = 256; dk0 = k0; }
    else if (bid < 128) { d = g_wvh;  dstride = 256; dk0 = k0; }
    else if (bid < 384) {
        if (k0 < 256) { d = g_w1f;  dstride = 512; dk0 = k0; }
        else          { d = g_w1bt; dstride = 256; dk0 = k0 - 256; }
    }
    else                { d = g_w2h;  dstride = 512; dk0 = k0; }
#pragma unroll
    for (int i = 0; i < 4; i++)
        d[(size_t)(n0 + ty + i * 8) * dstride + dk0 + tx] =
            __float2half_rn(t[tx][ty + i * 8]);
}

// ---------------- fused bias: g_bf = b1 + bo @ W1b ---------------------------
__global__ void bias_fuse(const float* __restrict__ b1, const float* __restrict__ bo,
                          const float* __restrict__ W1)
{
    int n = threadIdx.x;   // 512 threads
    float acc = b1[n];
    for (int j = 0; j < 256; j++)
        acc = fmaf(bo[j], W1[(size_t)(256 + j) * 512 + n], acc);
    g_bf[n] = acc;
}

// ---------------- fp16 mma GEMM, 128x128 block, K-tile 64, 3-stage -----------
// MODE 0: A=g_xh      -> g_qkh (scaled incl log2e)/g_vh
// MODE 2: A=[xh|amh]  -> g_h1 (+g_bf, fp32 raw)     (B = g_w1f: W1a^T | Wf^T)
// MODE 3: A=g_hg      -> out (+b2+residual)
// MODE 4: A=g_w1bt    -> g_w1f cols 256.. (Wf^T = W1b^T x Wo, prep)
template<int MODE>
__global__ void __launch_bounds__(256, 2) mgemm(
    const float* __restrict__ ba, const float* __restrict__ bb,
    const float* __restrict__ r0, const float* __restrict__ r1,
    float* __restrict__ out)
{
    constexpr int K   = (MODE == 2 || MODE == 3) ? 512 : 256;
    constexpr int LDA = (MODE == 3) ? 512 : 256;
    constexpr int KT  = K / 64;
    constexpr int STB = 36864;           // bytes/stage: A 18432 + B 18432

    extern __shared__ uint32_t sm[];
    const uint32_t smb = (uint32_t)__cvta_generic_to_shared(sm);
    const int tid = threadIdx.x, wid = tid >> 5, lane = tid & 31;
    const int wm = wid & 3, wn = wid >> 2, g = lane >> 2, t = lane & 3;
    const int bx = blockIdx.x, by = blockIdx.y;

    const __half* Bt;
    if constexpr (MODE == 0) Bt = (bx < 2) ? (g_wqkh + (size_t)bx * 128 * K)
                                           : (g_wvh + (size_t)(bx - 2) * 128 * K);
    else if constexpr (MODE == 2) Bt = g_w1f + (size_t)bx * 128 * K;
    else if constexpr (MODE == 3) Bt = g_w2h + (size_t)bx * 128 * K;
    else                          Bt = g_worm + (size_t)bx * 128 * K;

    auto copy_tile = [&](int kt, int st) {
        const int k0 = kt * 64;
        const __half* Ab;
        if constexpr (MODE == 0)      Ab = g_xh + k0;
        else if constexpr (MODE == 2) Ab = (k0 < 256) ? (g_xh + k0) : (g_amh + (k0 - 256));
        else if constexpr (MODE == 3) Ab = g_hg + k0;
        else                          Ab = g_w1bt + k0;
        Ab += (size_t)by * 128 * LDA;
        const __half* Bb = Bt + k0;
        uint32_t sA = smb + (uint32_t)st * STB;
        uint32_t sB = sA + 18432;
#pragma unroll
        for (int i = 0; i < 4; i++) {
            int ci = i * 256 + tid, row = ci >> 3, ch = ci & 7;
            cpa16(sA + (uint32_t)(row * 144 + ch * 16), Ab + (size_t)row * LDA + ch * 8);
            cpa16(sB + (uint32_t)(row * 144 + ch * 16), Bb + (size_t)row * K + ch * 8);
        }
        cp_commit();
    };

    const uint32_t aoff = (uint32_t)(wm * 32 + (lane & 15)) * 144 + ((lane >> 4) & 1) * 16;
    const uint32_t boff = (uint32_t)(wn * 64 + (lane & 7) + ((lane >> 4) & 1) * 8) * 144
                        + ((lane >> 3) & 1) * 16;

    float acc[2][8][4] = {};

    copy_tile(0, 0);
    copy_tile(1, 1);

    for (int kt = 0; kt < KT; kt++) {
        if (kt + 2 < KT) cp_wait<1>(); else cp_wait<0>();
        __syncthreads();
        if (kt + 2 < KT) copy_tile(kt + 2, (kt + 2) % 3);

        const uint32_t sA = smb + (uint32_t)((kt % 3) * STB);
        const uint32_t sB = sA + 18432;
#pragma unroll
        for (int ks = 0; ks < 4; ks++) {
            uint32_t af[2][4], bf[4][4];
            ldsm4(af[0], sA + aoff + ks * 32);
            ldsm4(af[1], sA + aoff + 2304 + ks * 32);
#pragma unroll
            for (int ntg = 0; ntg < 4; ntg++)
                ldsm4(bf[ntg], sB + boff + ntg * 2304 + ks * 32);
#pragma unroll
            for (int mt = 0; mt < 2; mt++)
#pragma unroll
                for (int nt = 0; nt < 8; nt++)
                    mma16(acc[mt][nt], af[mt], &bf[nt >> 1][(nt & 1) * 2]);
        }
    }

    // epilogue
#pragma unroll
    for (int mt = 0; mt < 2; mt++)
#pragma unroll
    for (int h = 0; h < 2; h++) {
        int r = by * 128 + wm * 32 + mt * 16 + g + h * 8;
#pragma unroll
        for (int nt = 0; nt < 8; nt++) {
            int c = bx * 128 + wn * 64 + nt * 8 + 2 * t;
            float v0 = acc[mt][nt][h * 2 + 0];
            float v1 = acc[mt][nt][h * 2 + 1];
            if constexpr (MODE == 0) {
                int src = r >> 13, rl = r & 8191;
                int b = rl >> 11, n = rl & 2047;
                if (c < 256) {
                    float2 b2 = *(const float2*)&ba[c];
                    int hh = c >> 6, d = c & 63;
                    uint32_t w = f2h2((v0 + b2.x) * QK_SCALE2, (v1 + b2.y) * QK_SCALE2);
                    *(uint32_t*)&g_qkh[src][(((size_t)(b * NH + hh)) * NN + n) * ND + d] = w;
                } else {
                    int c2 = c - 256;
                    float2 b2 = *(const float2*)&bb[c2];
                    int hh = c2 >> 6, d = c2 & 63;
                    uint32_t w = f2h2(v0 + b2.x, v1 + b2.y);
                    *(uint32_t*)&g_vh[src][(((size_t)(b * NH + hh)) * NN + n) * ND + d] = w;
                }
            } else if constexpr (MODE == 2) {
                float2 b2 = *(const float2*)&g_bf[c];
                float2 w; w.x = v0 + b2.x; w.y = v1 + b2.y;
                *(float2*)&g_h1[(size_t)r * NE2 + c] = w;
            } else if constexpr (MODE == 3) {
                int src = r >> 13, rl = r & 8191;
                const float* xr = src ? r1 : r0;
                float2 b2 = *(const float2*)&ba[c];
                float2 xv = *(const float2*)&xr[(size_t)rl * NE + c];
                float2 w; w.x = v0 + b2.x + xv.x; w.y = v1 + b2.y + xv.y;
                *(float2*)&out[(size_t)r * NE + c] = w;
            } else {    // MODE 4: Wf^T -> g_w1f cols 256..511, fp16
                *(uint32_t*)&g_w1f[(size_t)r * NE2 + 256 + c] = f2h2(v0, v1);
            }
        }
    }
}

// ---------------- flash attention fp16 (R13): ex2.f16x2, ones-column l -------
// block = 128 threads, Q-tile 128 rows, warp tile 32x64, 2-stage KV (64 rows)
__global__ void __launch_bounds__(128, 2) attn_mma()
{
    extern __shared__ uint32_t smx[];
    char* smc = (char*)smx;
    const uint32_t smb = (uint32_t)__cvta_generic_to_shared(smx);

    const int qt = blockIdx.x, bh = blockIdx.y, dir = blockIdx.z;
    const int tid = threadIdx.x, wid = tid >> 5, lane = tid & 31;
    const int g = lane >> 2, t = lane & 3, mq = wid * 32;

    const __half* Q  = g_qkh[dir]     + (size_t)bh * NN * ND + (size_t)qt * 128 * ND;
    const __half* Kp = g_qkh[dir ^ 1] + (size_t)bh * NN * ND;
    const __half* Vp = g_vh [dir ^ 1] + (size_t)bh * NN * ND;

    // ones-column init: V smem padding halves 64..71 = [1,0,0,0,0,0,0,0]
    {
        int st = tid >> 6, row = tid & 63;   // 128 threads = 2 stages x 64 rows
        *(uint4*)(smc + 18432 + st * 9216 + row * 144 + 128) =
            make_uint4(0x00003C00u, 0u, 0u, 0u);
    }

    // stage Q (128 rows x 64 halves) into K region, stride 144B
    {
        const uint4* qsrc = (const uint4*)(Q + (size_t)tid * ND);
#pragma unroll
        for (int i = 0; i < 8; i++)
            *(uint4*)(smc + tid * 144 + i * 16) = qsrc[i];
    }
    __syncthreads();

    uint32_t qf[2][4][4];
#pragma unroll
    for (int mt = 0; mt < 2; mt++)
#pragma unroll
        for (int ks = 0; ks < 4; ks++)
            ldsm4(qf[mt][ks],
                  smb + (uint32_t)(mq + mt * 16 + (lane & 15)) * 144
                      + ((lane >> 4) & 1) * 16 + ks * 32);
    __syncthreads();

    auto load_kv = [&](int j, int st) {
        uint32_t sK = smb + (uint32_t)st * 9216;
        uint32_t sV = smb + 18432 + (uint32_t)st * 9216;
        const __half* kb = Kp + (size_t)j * 64 * ND;
        const __half* vb = Vp + (size_t)j * 64 * ND;
#pragma unroll
        for (int i = 0; i < 4; i++) {     // 64 rows x 8 chunks = 512 / 128 thr
            int ci = i * 128 + tid, row = ci >> 3, ch = ci & 7;
            cpa16(sK + (uint32_t)(row * 144 + ch * 16), kb + row * 64 + ch * 8);
            cpa16(sV + (uint32_t)(row * 144 + ch * 16), vb + row * 64 + ch * 8);
        }
        cp_commit();
    };

    const uint32_t koff = (uint32_t)((lane & 7) + ((lane >> 4) & 1) * 8) * 144
                        + ((lane >> 3) & 1) * 16;               // K: B-pattern
    const uint32_t voff = (uint32_t)((lane & 7) + ((lane >> 3) & 1) * 8) * 144
                        + ((lane >> 4) & 1) * 16;               // V: trans pattern

    float o[2][9][4] = {};    // [..][8] = row-sum accumulator (ones column)

    load_kv(0, 0);

    for (int j = 0; j < 32; j++) {
        cp_wait<0>();
        __syncthreads();
        if (j + 1 < 32) load_kv(j + 1, (j + 1) & 1);

        const uint32_t sK = smb + (uint32_t)((j & 1) * 9216);
        const uint32_t sV = smb + 18432 + (uint32_t)((j & 1) * 9216);

        // S = Q K^T (32 x 64 per warp); S is already in log2 domain
        float s[2][8][4] = {};
#pragma unroll
        for (int ks = 0; ks < 4; ks++) {
            uint32_t kf[4][4];
#pragma unroll
            for (int ntg = 0; ntg < 4; ntg++)
                ldsm4(kf[ntg], sK + koff + ntg * 2304 + ks * 32);
#pragma unroll
            for (int mt = 0; mt < 2; mt++)
#pragma unroll
                for (int nt = 0; nt < 8; nt++)
                    mma16(s[mt][nt], qf[mt][ks], &kf[nt >> 1][(nt & 1) * 2]);
        }

        // P = ex2(S) in fp16x2; fragments are natural acc pairs
        uint32_t pf[2][4][4];
#pragma unroll
        for (int mt = 0; mt < 2; mt++)
#pragma unroll
        for (int kvg = 0; kvg < 4; kvg++) {
            pf[mt][kvg][0] = hex2(f2h2(s[mt][2*kvg][0],   s[mt][2*kvg][1]));
            pf[mt][kvg][1] = hex2(f2h2(s[mt][2*kvg][2],   s[mt][2*kvg][3]));
            pf[mt][kvg][2] = hex2(f2h2(s[mt][2*kvg+1][0], s[mt][2*kvg+1][1]));
            pf[mt][kvg][3] = hex2(f2h2(s[mt][2*kvg+1][2], s[mt][2*kvg+1][3]));
        }

        // O += P V ; 9th fragment (cols 64..71, ones at 64) accumulates l
#pragma unroll
        for (int kvg = 0; kvg < 4; kvg++) {
            uint32_t vf[5][4];
#pragma unroll
            for (int ntg = 0; ntg < 5; ntg++)
                ldsm4t(vf[ntg], sV + voff + (uint32_t)kvg * 2304 + ntg * 32);
#pragma unroll
            for (int mt = 0; mt < 2; mt++) {
#pragma unroll
                for (int nt = 0; nt < 8; nt++)
                    mma16(o[mt][nt], pf[mt][kvg], &vf[nt >> 1][(nt & 1) * 2]);
                mma16(o[mt][8], pf[mt][kvg], &vf[4][0]);
            }
        }
    }

    const int b = bh >> 2, hd = bh & 3;
#pragma unroll
    for (int mt = 0; mt < 2; mt++)
#pragma unroll
    for (int h = 0; h < 2; h++) {
        // l lives in o[mt][8][2h] of lanes with t==0 (column 64); broadcast
        float l = __shfl_sync(0xffffffffu, o[mt][8][2 * h], lane & 28);
        float inv = 1.f / l;
        int n = qt * 128 + mq + mt * 16 + g + h * 8;
        size_t base = ((size_t)(dir * 8192 + b * NN + n)) * NE + hd * ND;
#pragma unroll
        for (int nt = 0; nt < 8; nt++) {
            uint32_t w = f2h2(o[mt][nt][2 * h] * inv, o[mt][nt][2 * h + 1] * inv);
            *(uint32_t*)&g_amh[base + nt * 8 + 2 * t] = w;
        }
    }
}

// ---------------- LayerNorm(512) + exact GELU: g_h1 fp32 -> g_hg fp16 --------
__global__ void __launch_bounds__(128) ln_gelu_kernel(
    const float* __restrict__ gvec, const float* __restrict__ bvec)
{
    const float* p = g_h1 + (size_t)blockIdx.x * NE2;
    int t = threadIdx.x;
    float4 v = ((const float4*)p)[t];
    float s = v.x + v.y + v.z + v.w;
    float q = v.x * v.x + v.y * v.y + v.z * v.z + v.w * v.w;
#pragma unroll
    for (int off = 16; off > 0; off >>= 1) {
        s += __shfl_xor_sync(0xffffffffu, s, off);
        q += __shfl_xor_sync(0xffffffffu, q, off);
    }
    __shared__ float rs_[4], rq_[4];
    if ((t & 31) == 0) { rs_[t >> 5] = s; rq_[t >> 5] = q; }
    __syncthreads();
    s = rs_[0] + rs_[1] + rs_[2] + rs_[3];
    q = rq_[0] + rq_[1] + rq_[2] + rq_[3];
    float mean = s * (1.f / 512.f);
    float var = q * (1.f / 512.f) - mean * mean;
    float r = rsqrtf(var + 1e-5f);
    float4 gv = ((const float4*)gvec)[t];
    float4 bv = ((const float4*)bvec)[t];
    float xn;
    xn = (v.x - mean) * r * gv.x + bv.x; v.x = 0.5f * xn * (1.f + erff(xn * 0.70710678118654752f));
    xn = (v.y - mean) * r * gv.y + bv.y; v.y = 0.5f * xn * (1.f + erff(xn * 0.70710678118654752f));
    xn = (v.z - mean) * r * gv.z + bv.z; v.z = 0.5f * xn * (1.f + erff(xn * 0.70710678118654752f));
    xn = (v.w - mean) * r * gv.w + bv.w; v.w = 0.5f * xn * (1.f + erff(xn * 0.70710678118654752f));
    uint2 w; w.x = f2h2(v.x, v.y); w.y = f2h2(v.z, v.w);
    ((uint2*)&g_hg[(size_t)blockIdx.x * NE2])[t] = w;
}

// ---------------------------------------------------------------------------
extern "C" void kernel_launch(void* const* d_in, const int* in_sizes, int n_in,
                              void* d_out, int out_size)
{
    const float* x0  = (const float*)d_in[0];
    const float* x1  = (const float*)d_in[1];
    const float* Wqk = (const float*)d_in[2];
    const float* bqk = (const float*)d_in[3];
    const float* Wv  = (const float*)d_in[4];
    const float* bv  = (const float*)d_in[5];
    const float* Wo  = (const float*)d_in[6];
    const float* bo  = (const float*)d_in[7];
    const float* W1  = (const float*)d_in[8];
    const float* b1  = (const float*)d_in[9];
    const float* lng = (const float*)d_in[10];
    const float* lnb = (const float*)d_in[11];
    const float* W2  = (const float*)d_in[12];
    const float* b2  = (const float*)d_in[13];
    float* out = (float*)d_out;
    (void)in_sizes; (void)n_in; (void)out_size;

    const int GEMM_SMEM = 110592;   // 3 stages x 36864 B -> 2 blocks/SM
    const int ATTN_SMEM = 37120;    // 36864 + pad for ntg=4 ldsm overread
    cudaFuncSetAttribute(mgemm<0>, cudaFuncAttributeMaxDynamicSharedMemorySize, GEMM_SMEM);
    cudaFuncSetAttribute(mgemm<2>, cudaFuncAttributeMaxDynamicSharedMemorySize, GEMM_SMEM);
    cudaFuncSetAttribute(mgemm<3>, cudaFuncAttributeMaxDynamicSharedMemorySize, GEMM_SMEM);
    cudaFuncSetAttribute(mgemm<4>, cudaFuncAttributeMaxDynamicSharedMemorySize, GEMM_SMEM);
    cudaFuncSetAttribute(attn_mma, cudaFuncAttributeMaxDynamicSharedMemorySize, ATTN_SMEM);

    // 0) convert x + weights; build fused W1' = [W1a | Wo@W1b] and bias
    cvt_x<<<2048, 256>>>(x0, x1);
    cvt_wT_all<<<576, 256>>>(Wqk, Wv, Wo, W1, W2);
    bias_fuse<<<1, 512>>>(b1, bo, W1);
    mgemm<4><<<dim3(2, 4), 256, GEMM_SMEM>>>(nullptr, nullptr, nullptr, nullptr, nullptr);

    // 1) fused qk/v projection (qk scaled by 64^-.25 * sqrt(log2e))
    mgemm<0><<<dim3(4, 128), 256, GEMM_SMEM>>>(bqk, bv, x0, x1, nullptr);
    // 2) bidirectional flash attention (R13: ex2.f16x2 + ones-column l)
    attn_mma<<<dim3(16, 16, 2), 128, ATTN_SMEM>>>();
    // 3) FFN GEMM1 fused: [x | m] @ [W1a ; Wo@W1b] + (b1 + bo@W1b) -> g_h1
    mgemm<2><<<dim3(4, 128), 256, GEMM_SMEM>>>(nullptr, nullptr, x0, x1, nullptr);
    // 4) LayerNorm + GELU -> g_hg fp16
    ln_gelu_kernel<<<16384, 128>>>(lng, lnb);
    // 5) FFN GEMM2 + bias + residual -> out
    mgemm<3><<<dim3(2, 128), 256, GEMM_SMEM>>>(b2, nullptr, x0, x1, out);
}

// round 17
// speedup vs baseline: 1.0426x; 1.0426x over previous
#include <cuda_runtime.h>
#include <cuda_fp16.h>
#include <cstdint>

#define NB 4
#define NN 2048
#define NE 256
#define NH 4
#define ND 64
#define NE2 512
#define NTOK 16384               // 2 * B * N
#define PER (NB*NH*NN*ND)
// 64^-0.25 * sqrt(log2(e)) — folds exp->exp2 conversion into both q and k
#define QK_SCALE2 0.4246609001428604f

// ---------------- scratch (device globals; no allocation allowed) ----------
__device__ __half g_qkh[2][PER];          // fp16 q/k (scaled, incl sqrt(log2e))
__device__ __half g_vh [2][PER];          // fp16 v
__device__ __half g_amh[NTOK*NE];         // attention out fp16
__device__ __half g_moh[NTOK*NE];         // m @ Wo + bo fp16
__device__ float  g_h1 [NTOK*NE2];        // FFN1 out raw fp32
__device__ __half g_hg [NTOK*NE2];        // LN+gelu out fp16
__device__ __half g_xh [NTOK*NE];         // x0|x1 fp16
// weights TRANSPOSED [n][k] fp16
__device__ __half g_wqkh[NE*NE], g_wvh[NE*NE], g_woh[NE*NE];
__device__ __half g_w1h[NE2*NE2], g_w2h[NE2*NE];

// ---------------- helpers ---------------------------------------------------
__device__ __forceinline__ uint32_t f2h2(float lo, float hi) {
    uint32_t r; asm("cvt.rn.f16x2.f32 %0, %1, %2;" : "=r"(r) : "f"(hi), "f"(lo));
    return r;
}
__device__ __forceinline__ uint32_t hex2(uint32_t x) {
    uint32_t r; asm("ex2.approx.f16x2 %0, %1;" : "=r"(r) : "r"(x)); return r;
}
__device__ __forceinline__ void cpa16(uint32_t s, const void* g) {
    asm volatile("cp.async.cg.shared.global [%0], [%1], 16;" :: "r"(s), "l"(g));
}
__device__ __forceinline__ void cp_commit() { asm volatile("cp.async.commit_group;"); }
template<int N> __device__ __forceinline__ void cp_wait() {
    asm volatile("cp.async.wait_group %0;" :: "n"(N));
}
__device__ __forceinline__ void mma16(float* d, const uint32_t* a, const uint32_t* b) {
    asm("mma.sync.aligned.m16n8k16.row.col.f32.f16.f16.f32 "
        "{%0,%1,%2,%3}, {%4,%5,%6,%7}, {%8,%9}, {%0,%1,%2,%3};\n"
        : "+f"(d[0]), "+f"(d[1]), "+f"(d[2]), "+f"(d[3])
        : "r"(a[0]), "r"(a[1]), "r"(a[2]), "r"(a[3]), "r"(b[0]), "r"(b[1]));
}
__device__ __forceinline__ void ldsm4(uint32_t* r, uint32_t addr) {
    asm("ldmatrix.sync.aligned.m8n8.x4.shared.b16 {%0,%1,%2,%3}, [%4];"
        : "=r"(r[0]), "=r"(r[1]), "=r"(r[2]), "=r"(r[3]) : "r"(addr));
}
__device__ __forceinline__ void ldsm4t(uint32_t* r, uint32_t addr) {
    asm("ldmatrix.sync.aligned.m8n8.x4.trans.shared.b16 {%0,%1,%2,%3}, [%4];"
        : "=r"(r[0]), "=r"(r[1]), "=r"(r[2]), "=r"(r[3]) : "r"(addr));
}

// ---------------- ALL conversions in ONE launch ------------------------------
// blocks 0..575: weight transposes (W[k][n] fp32 -> Wt[n][k] fp16)
// blocks 576..2623: x0|x1 fp32 -> fp16
__global__ void cvt_all(const float* __restrict__ x0,  const float* __restrict__ x1,
                        const float* __restrict__ Wqk, const float* __restrict__ Wv,
                        const float* __restrict__ Wo,  const float* __restrict__ W1,
                        const float* __restrict__ W2)
{
    int bid = blockIdx.x;
    if (bid >= 576) {
        int i = (bid - 576) * 256 + threadIdx.x;    // 8-elem chunks, 524288 total
        const float4* s = (i < 262144) ? (const float4*)x0 : (const float4*)x1;
        int j = (i < 262144) ? i : i - 262144;
        float4 a = s[2 * j], b = s[2 * j + 1];
        uint4 o;
        o.x = f2h2(a.x, a.y); o.y = f2h2(a.z, a.w);
        o.z = f2h2(b.x, b.y); o.w = f2h2(b.z, b.w);
        ((uint4*)g_xh)[i] = o;
        return;
    }
    __shared__ float t[32][33];
    const float* s; __half* d; int K, N, tile;
    if (bid < 64)       { s = Wqk; d = g_wqkh; K = 256; N = 256; tile = bid; }
    else if (bid < 128) { s = Wv;  d = g_wvh;  K = 256; N = 256; tile = bid - 64; }
    else if (bid < 192) { s = Wo;  d = g_woh;  K = 256; N = 256; tile = bid - 128; }
    else if (bid < 448) { s = W1;  d = g_w1h;  K = 512; N = 512; tile = bid - 192; }
    else                { s = W2;  d = g_w2h;  K = 512; N = 256; tile = bid - 448; }
    int tn = N / 32;
    int k0 = (tile / tn) * 32, n0 = (tile % tn) * 32;
    int tx = threadIdx.x & 31, ty = threadIdx.x >> 5;   // 256 threads = 32x8
#pragma unroll
    for (int i = 0; i < 4; i++)
        t[ty + i * 8][tx] = s[(size_t)(k0 + ty + i * 8) * N + n0 + tx];
    __syncthreads();
#pragma unroll
    for (int i = 0; i < 4; i++)
        d[(size_t)(n0 + ty + i * 8) * K + k0 + tx] = __float2half_rn(t[tx][ty + i * 8]);
}

// ---------------- fp16 mma GEMM, 128x128 block, K-tile 64, 3-stage -----------
// MODE 0: A=g_xh   -> g_qkh (scaled incl log2e)/g_vh   MODE 1: A=g_amh -> g_moh
// MODE 2: A=[xh|mo]-> g_h1 (+b1, fp32 raw)             MODE 3: A=g_hg  -> out
template<int MODE>
__global__ void __launch_bounds__(256, 2) mgemm(
    const float* __restrict__ ba, const float* __restrict__ bb,
    const float* __restrict__ r0, const float* __restrict__ r1,
    float* __restrict__ out)
{
    constexpr int K   = (MODE >= 2) ? 512 : 256;
    constexpr int LDA = (MODE == 3) ? 512 : 256;
    constexpr int KT  = K / 64;
    constexpr int STB = 36864;           // bytes/stage: A 18432 + B 18432

    extern __shared__ uint32_t sm[];
    const uint32_t smb = (uint32_t)__cvta_generic_to_shared(sm);
    const int tid = threadIdx.x, wid = tid >> 5, lane = tid & 31;
    const int wm = wid & 3, wn = wid >> 2, g = lane >> 2, t = lane & 3;
    const int bx = blockIdx.x, by = blockIdx.y;

    const __half* Bt;
    if constexpr (MODE == 0) Bt = (bx < 2) ? (g_wqkh + (size_t)bx * 128 * K)
                                           : (g_wvh + (size_t)(bx - 2) * 128 * K);
    else if constexpr (MODE == 1) Bt = g_woh + (size_t)bx * 128 * K;
    else if constexpr (MODE == 2) Bt = g_w1h + (size_t)bx * 128 * K;
    else                          Bt = g_w2h + (size_t)bx * 128 * K;

    auto copy_tile = [&](int kt, int st) {
        const int k0 = kt * 64;
        const __half* Ab;
        if constexpr (MODE == 0)      Ab = g_xh + k0;
        else if constexpr (MODE == 1) Ab = g_amh + k0;
        else if constexpr (MODE == 2) Ab = (k0 < 256) ? (g_xh + k0) : (g_moh + (k0 - 256));
        else                          Ab = g_hg + k0;
        Ab += (size_t)by * 128 * LDA;
        const __half* Bb = Bt + k0;
        uint32_t sA = smb + (uint32_t)st * STB;
        uint32_t sB = sA + 18432;
#pragma unroll
        for (int i = 0; i < 4; i++) {
            int ci = i * 256 + tid, row = ci >> 3, ch = ci & 7;
            cpa16(sA + (uint32_t)(row * 144 + ch * 16), Ab + (size_t)row * LDA + ch * 8);
            cpa16(sB + (uint32_t)(row * 144 + ch * 16), Bb + (size_t)row * K + ch * 8);
        }
        cp_commit();
    };

    const uint32_t aoff = (uint32_t)(wm * 32 + (lane & 15)) * 144 + ((lane >> 4) & 1) * 16;
    const uint32_t boff = (uint32_t)(wn * 64 + (lane & 7) + ((lane >> 4) & 1) * 8) * 144
                        + ((lane >> 3) & 1) * 16;

    float acc[2][8][4] = {};

    copy_tile(0, 0);
    copy_tile(1, 1);

    for (int kt = 0; kt < KT; kt++) {
        if (kt + 2 < KT) cp_wait<1>(); else cp_wait<0>();
        __syncthreads();
        if (kt + 2 < KT) copy_tile(kt + 2, (kt + 2) % 3);

        const uint32_t sA = smb + (uint32_t)((kt % 3) * STB);
        const uint32_t sB = sA + 18432;
#pragma unroll
        for (int ks = 0; ks < 4; ks++) {
            uint32_t af[2][4], bf[4][4];
            ldsm4(af[0], sA + aoff + ks * 32);
            ldsm4(af[1], sA + aoff + 2304 + ks * 32);
#pragma unroll
            for (int ntg = 0; ntg < 4; ntg++)
                ldsm4(bf[ntg], sB + boff + ntg * 2304 + ks * 32);
#pragma unroll
            for (int mt = 0; mt < 2; mt++)
#pragma unroll
                for (int nt = 0; nt < 8; nt++)
                    mma16(acc[mt][nt], af[mt], &bf[nt >> 1][(nt & 1) * 2]);
        }
    }

    // epilogue
#pragma unroll
    for (int mt = 0; mt < 2; mt++)
#pragma unroll
    for (int h = 0; h < 2; h++) {
        int r = by * 128 + wm * 32 + mt * 16 + g + h * 8;
#pragma unroll
        for (int nt = 0; nt < 8; nt++) {
            int c = bx * 128 + wn * 64 + nt * 8 + 2 * t;
            float v0 = acc[mt][nt][h * 2 + 0];
            float v1 = acc[mt][nt][h * 2 + 1];
            if constexpr (MODE == 0) {
                int src = r >> 13, rl = r & 8191;
                int b = rl >> 11, n = rl & 2047;
                if (c < 256) {
                    float2 b2 = *(const float2*)&ba[c];
                    int hh = c >> 6, d = c & 63;
                    uint32_t w = f2h2((v0 + b2.x) * QK_SCALE2, (v1 + b2.y) * QK_SCALE2);
                    *(uint32_t*)&g_qkh[src][(((size_t)(b * NH + hh)) * NN + n) * ND + d] = w;
                } else {
                    int c2 = c - 256;
                    float2 b2 = *(const float2*)&bb[c2];
                    int hh = c2 >> 6, d = c2 & 63;
                    uint32_t w = f2h2(v0 + b2.x, v1 + b2.y);
                    *(uint32_t*)&g_vh[src][(((size_t)(b * NH + hh)) * NN + n) * ND + d] = w;
                }
            } else if constexpr (MODE == 1) {
                float2 b2 = *(const float2*)&ba[c];
                uint32_t w = f2h2(v0 + b2.x, v1 + b2.y);
                *(uint32_t*)&g_moh[(size_t)r * NE + c] = w;
            } else if constexpr (MODE == 2) {
                float2 b2 = *(const float2*)&ba[c];
                float2 w; w.x = v0 + b2.x; w.y = v1 + b2.y;
                *(float2*)&g_h1[(size_t)r * NE2 + c] = w;
            } else {
                int src = r >> 13, rl = r & 8191;
                const float* xr = src ? r1 : r0;
                float2 b2 = *(const float2*)&ba[c];
                float2 xv = *(const float2*)&xr[(size_t)rl * NE + c];
                float2 w; w.x = v0 + b2.x + xv.x; w.y = v1 + b2.y + xv.y;
                *(float2*)&out[(size_t)r * NE + c] = w;
            }
        }
    }
}

// ---------------- flash attention fp16 (R13): ex2.f16x2, ones-column l -------
// block = 128 threads, Q-tile 128 rows, warp tile 32x64, 2-stage KV (64 rows)
__global__ void __launch_bounds__(128, 2) attn_mma()
{
    extern __shared__ uint32_t smx[];
    char* smc = (char*)smx;
    const uint32_t smb = (uint32_t)__cvta_generic_to_shared(smx);

    const int qt = blockIdx.x, bh = blockIdx.y, dir = blockIdx.z;
    const int tid = threadIdx.x, wid = tid >> 5, lane = tid & 31;
    const int g = lane >> 2, t = lane & 3, mq = wid * 32;

    const __half* Q  = g_qkh[dir]     + (size_t)bh * NN * ND + (size_t)qt * 128 * ND;
    const __half* Kp = g_qkh[dir ^ 1] + (size_t)bh * NN * ND;
    const __half* Vp = g_vh [dir ^ 1] + (size_t)bh * NN * ND;

    // ones-column init: V smem padding halves 64..71 = [1,0,0,0,0,0,0,0]
    {
        int st = tid >> 6, row = tid & 63;   // 128 threads = 2 stages x 64 rows
        *(uint4*)(smc + 18432 + st * 9216 + row * 144 + 128) =
            make_uint4(0x00003C00u, 0u, 0u, 0u);
    }

    // stage Q (128 rows x 64 halves) into K region, stride 144B
    {
        const uint4* qsrc = (const uint4*)(Q + (size_t)tid * ND);
#pragma unroll
        for (int i = 0; i < 8; i++)
            *(uint4*)(smc + tid * 144 + i * 16) = qsrc[i];
    }
    __syncthreads();

    uint32_t qf[2][4][4];
#pragma unroll
    for (int mt = 0; mt < 2; mt++)
#pragma unroll
        for (int ks = 0; ks < 4; ks++)
            ldsm4(qf[mt][ks],
                  smb + (uint32_t)(mq + mt * 16 + (lane & 15)) * 144
                      + ((lane >> 4) & 1) * 16 + ks * 32);
    __syncthreads();

    auto load_kv = [&](int j, int st) {
        uint32_t sK = smb + (uint32_t)st * 9216;
        uint32_t sV = smb + 18432 + (uint32_t)st * 9216;
        const __half* kb = Kp + (size_t)j * 64 * ND;
        const __half* vb = Vp + (size_t)j * 64 * ND;
#pragma unroll
        for (int i = 0; i < 4; i++) {     // 64 rows x 8 chunks = 512 / 128 thr
            int ci = i * 128 + tid, row = ci >> 3, ch = ci & 7;
            cpa16(sK + (uint32_t)(row * 144 + ch * 16), kb + row * 64 + ch * 8);
            cpa16(sV + (uint32_t)(row * 144 + ch * 16), vb + row * 64 + ch * 8);
        }
        cp_commit();
    };

    const uint32_t koff = (uint32_t)((lane & 7) + ((lane >> 4) & 1) * 8) * 144
                        + ((lane >> 3) & 1) * 16;               // K: B-pattern
    const uint32_t voff = (uint32_t)((lane & 7) + ((lane >> 3) & 1) * 8) * 144
                        + ((lane >> 4) & 1) * 16;               // V: trans pattern

    float o[2][9][4] = {};    // [..][8] = row-sum accumulator (ones column)

    load_kv(0, 0);

    for (int j = 0; j < 32; j++) {
        cp_wait<0>();
        __syncthreads();
        if (j + 1 < 32) load_kv(j + 1, (j + 1) & 1);

        const uint32_t sK = smb + (uint32_t)((j & 1) * 9216);
        const uint32_t sV = smb + 18432 + (uint32_t)((j & 1) * 9216);

        // S = Q K^T (32 x 64 per warp); S is already in log2 domain
        float s[2][8][4] = {};
#pragma unroll
        for (int ks = 0; ks < 4; ks++) {
            uint32_t kf[4][4];
#pragma unroll
            for (int ntg = 0; ntg < 4; ntg++)
                ldsm4(kf[ntg], sK + koff + ntg * 2304 + ks * 32);
#pragma unroll
            for (int mt = 0; mt < 2; mt++)
#pragma unroll
                for (int nt = 0; nt < 8; nt++)
                    mma16(s[mt][nt], qf[mt][ks], &kf[nt >> 1][(nt & 1) * 2]);
        }

        // P = ex2(S) in fp16x2; fragments are natural acc pairs
        uint32_t pf[2][4][4];
#pragma unroll
        for (int mt = 0; mt < 2; mt++)
#pragma unroll
        for (int kvg = 0; kvg < 4; kvg++) {
            pf[mt][kvg][0] = hex2(f2h2(s[mt][2*kvg][0],   s[mt][2*kvg][1]));
            pf[mt][kvg][1] = hex2(f2h2(s[mt][2*kvg][2],   s[mt][2*kvg][3]));
            pf[mt][kvg][2] = hex2(f2h2(s[mt][2*kvg+1][0], s[mt][2*kvg+1][1]));
            pf[mt][kvg][3] = hex2(f2h2(s[mt][2*kvg+1][2], s[mt][2*kvg+1][3]));
        }

        // O += P V ; 9th fragment (cols 64..71, ones at 64) accumulates l
#pragma unroll
        for (int kvg = 0; kvg < 4; kvg++) {
            uint32_t vf[5][4];
#pragma unroll
            for (int ntg = 0; ntg < 5; ntg++)
                ldsm4t(vf[ntg], sV + voff + (uint32_t)kvg * 2304 + ntg * 32);
#pragma unroll
            for (int mt = 0; mt < 2; mt++) {
#pragma unroll
                for (int nt = 0; nt < 8; nt++)
                    mma16(o[mt][nt], pf[mt][kvg], &vf[nt >> 1][(nt & 1) * 2]);
                mma16(o[mt][8], pf[mt][kvg], &vf[4][0]);
            }
        }
    }

    const int b = bh >> 2, hd = bh & 3;
#pragma unroll
    for (int mt = 0; mt < 2; mt++)
#pragma unroll
    for (int h = 0; h < 2; h++) {
        // l lives in o[mt][8][2h] of lanes with t==0 (column 64); broadcast
        float l = __shfl_sync(0xffffffffu, o[mt][8][2 * h], lane & 28);
        float inv = 1.f / l;
        int n = qt * 128 + mq + mt * 16 + g + h * 8;
        size_t base = ((size_t)(dir * 8192 + b * NN + n)) * NE + hd * ND;
#pragma unroll
        for (int nt = 0; nt < 8; nt++) {
            uint32_t w = f2h2(o[mt][nt][2 * h] * inv, o[mt][nt][2 * h + 1] * inv);
            *(uint32_t*)&g_amh[base + nt * 8 + 2 * t] = w;
        }
    }
}

// ---------------- LayerNorm(512) + exact GELU, 2 rows per block --------------
__global__ void __launch_bounds__(256) ln_gelu_kernel(
    const float* __restrict__ gvec, const float* __restrict__ bvec)
{
    const int r = threadIdx.x >> 7, t = threadIdx.x & 127;
    const size_t row = (size_t)blockIdx.x * 2 + r;
    const float* p = g_h1 + row * NE2;
    float4 v = ((const float4*)p)[t];
    float s = v.x + v.y + v.z + v.w;
    float q = v.x * v.x + v.y * v.y + v.z * v.z + v.w * v.w;
#pragma unroll
    for (int off = 16; off > 0; off >>= 1) {
        s += __shfl_xor_sync(0xffffffffu, s, off);
        q += __shfl_xor_sync(0xffffffffu, q, off);
    }
    __shared__ float rs_[2][4], rq_[2][4];
    if ((t & 31) == 0) { rs_[r][t >> 5] = s; rq_[r][t >> 5] = q; }
    __syncthreads();
    s = rs_[r][0] + rs_[r][1] + rs_[r][2] + rs_[r][3];
    q = rq_[r][0] + rq_[r][1] + rq_[r][2] + rq_[r][3];
    float mean = s * (1.f / 512.f);
    float var = q * (1.f / 512.f) - mean * mean;
    float rc = rsqrtf(var + 1e-5f);
    float4 gv = ((const float4*)gvec)[t];
    float4 bv = ((const float4*)bvec)[t];
    float xn;
    xn = (v.x - mean) * rc * gv.x + bv.x; v.x = 0.5f * xn * (1.f + erff(xn * 0.70710678118654752f));
    xn = (v.y - mean) * rc * gv.y + bv.y; v.y = 0.5f * xn * (1.f + erff(xn * 0.70710678118654752f));
    xn = (v.z - mean) * rc * gv.z + bv.z; v.z = 0.5f * xn * (1.f + erff(xn * 0.70710678118654752f));
    xn = (v.w - mean) * rc * gv.w + bv.w; v.w = 0.5f * xn * (1.f + erff(xn * 0.70710678118654752f));
    uint2 w; w.x = f2h2(v.x, v.y); w.y = f2h2(v.z, v.w);
    ((uint2*)&g_hg[row * NE2])[t] = w;
}

// ---------------------------------------------------------------------------
extern "C" void kernel_launch(void* const* d_in, const int* in_sizes, int n_in,
                              void* d_out, int out_size)
{
    const float* x0  = (const float*)d_in[0];
    const float* x1  = (const float*)d_in[1];
    const float* Wqk = (const float*)d_in[2];
    const float* bqk = (const float*)d_in[3];
    const float* Wv  = (const float*)d_in[4];
    const float* bv  = (const float*)d_in[5];
    const float* Wo  = (const float*)d_in[6];
    const float* bo  = (const float*)d_in[7];
    const float* W1  = (const float*)d_in[8];
    const float* b1  = (const float*)d_in[9];
    const float* lng = (const float*)d_in[10];
    const float* lnb = (const float*)d_in[11];
    const float* W2  = (const float*)d_in[12];
    const float* b2  = (const float*)d_in[13];
    float* out = (float*)d_out;
    (void)in_sizes; (void)n_in; (void)out_size;

    const int GEMM_SMEM = 110592;   // 3 stages x 36864 B -> 2 blocks/SM
    const int ATTN_SMEM = 37120;    // 36864 + pad for ntg=4 ldsm overread
    cudaFuncSetAttribute(mgemm<0>, cudaFuncAttributeMaxDynamicSharedMemorySize, GEMM_SMEM);
    cudaFuncSetAttribute(mgemm<1>, cudaFuncAttributeMaxDynamicSharedMemorySize, GEMM_SMEM);
    cudaFuncSetAttribute(mgemm<2>, cudaFuncAttributeMaxDynamicSharedMemorySize, GEMM_SMEM);
    cudaFuncSetAttribute(mgemm<3>, cudaFuncAttributeMaxDynamicSharedMemorySize, GEMM_SMEM);
    cudaFuncSetAttribute(attn_mma, cudaFuncAttributeMaxDynamicSharedMemorySize, ATTN_SMEM);

    // 0) convert x + transpose/convert all weights (ONE launch)
    cvt_all<<<2624, 256>>>(x0, x1, Wqk, Wv, Wo, W1, W2);

    // 1) fused qk/v projection (qk scaled by 64^-.25 * sqrt(log2e))
    mgemm<0><<<dim3(4, 128), 256, GEMM_SMEM>>>(bqk, bv, x0, x1, nullptr);
    // 2) bidirectional flash attention (ex2.f16x2 + ones-column l)
    attn_mma<<<dim3(16, 16, 2), 128, ATTN_SMEM>>>();
    // 3) Wo projection -> g_moh
    mgemm<1><<<dim3(2, 128), 256, GEMM_SMEM>>>(bo, nullptr, x0, x1, nullptr);
    // 4) FFN GEMM1 ([x | mo] @ W1) -> g_h1 (fp32 raw)
    mgemm<2><<<dim3(4, 128), 256, GEMM_SMEM>>>(b1, nullptr, x0, x1, nullptr);
    // 5) LayerNorm + GELU -> g_hg fp16 (2 rows/block)
    ln_gelu_kernel<<<8192, 256>>>(lng, lnb);
    // 6) FFN GEMM2 + bias + residual -> out
    mgemm<3><<<dim3(2, 128), 256, GEMM_SMEM>>>(b2, nullptr, x0, x1, out);
}